// round 16
// baseline (speedup 1.0000x reference)
#include <cuda_runtime.h>
#include <cuda_bf16.h>
#include <cuda_fp16.h>
#include <math.h>
#include <stdint.h>

#define N_NODES 100000
#define N_EDGES 1600000
#define HID 128
#define BN_EPS 1e-5f
#define N_TILES ((N_NODES + 127) / 128)   // 782

// ---------------- device scratch ----------------
__device__ __align__(16) __half g_ph[(size_t)N_NODES * HID];  // p = h@wl, fp16 (gather target)
__device__ __align__(16) float g_q[(size_t)N_NODES * HID];    // q = h@wr, fp32
__device__ __align__(16) __nv_bfloat16 g_ahi[(size_t)N_NODES * 192];  // activation hi
__device__ __align__(16) __nv_bfloat16 g_alo[(size_t)N_NODES * 192];  // activation lo
__device__ __align__(16) __nv_bfloat16 g_bhi[256 * 192];     // weight^T hi  [n][k]
__device__ __align__(16) __nv_bfloat16 g_blo[256 * 192];     // weight^T lo
__device__ int g_rowptr[N_NODES + 1];
__device__ int g_cursor[N_NODES];
__device__ int g_srcs[N_EDGES];

static __device__ __forceinline__ uint32_t sw128(uint32_t b) { return b ^ ((b >> 3) & 0x70u); }
__device__ __forceinline__ uint32_t smem_to_u32(const void* p) {
    uint32_t a;
    asm("{ .reg .u64 t; cvta.to.shared.u64 t, %1; cvt.u32.u64 %0, t; }" : "=r"(a) : "l"(p));
    return a;
}

// ---------------- CSR build ----------------
__global__ void k_zero_deg() {
    int i = blockIdx.x * blockDim.x + threadIdx.x;
    if (i < N_NODES) g_cursor[i] = 0;
}
__global__ void k_hist(const int* __restrict__ ei) {
    int e = blockIdx.x * blockDim.x + threadIdx.x;
    if (e < N_EDGES) {
        int dst = ei[N_EDGES + e];
        if (dst >= 0 && dst < N_NODES) atomicAdd(&g_cursor[dst], 1);
    }
}
__global__ void k_scan() {
    __shared__ int sums[1024];
    const int CH = (N_NODES + 1023) / 1024;
    int t = threadIdx.x;
    int lo = t * CH, hi = min(lo + CH, N_NODES);
    int s = 0;
    for (int i = lo; i < hi; ++i) s += g_cursor[i];
    sums[t] = s;
    __syncthreads();
    for (int off = 1; off < 1024; off <<= 1) {
        int v = (t >= off) ? sums[t - off] : 0;
        __syncthreads();
        sums[t] += v;
        __syncthreads();
    }
    int run = (t == 0) ? 0 : sums[t - 1];
    for (int i = lo; i < hi; ++i) {
        int d = g_cursor[i];
        g_rowptr[i] = run;
        run += d;
    }
    if (t == 1023) g_rowptr[N_NODES] = sums[1023];
}
__global__ void k_cursor_init() {
    int i = blockIdx.x * blockDim.x + threadIdx.x;
    if (i < N_NODES) g_cursor[i] = g_rowptr[i];
}
__global__ void k_place(const int* __restrict__ ei) {
    int e = blockIdx.x * blockDim.x + threadIdx.x;
    if (e < N_EDGES) {
        int src = ei[e];
        int dst = ei[N_EDGES + e];
        if (dst >= 0 && dst < N_NODES && src >= 0 && src < N_NODES) {
            int pos = atomicAdd(&g_cursor[dst], 1);
            if (pos >= 0 && pos < N_EDGES) g_srcs[pos] = src;
        }
    }
}

// ---------------- bf16 hi/lo split ----------------
__device__ __forceinline__ void split2(float f0, float f1, uint32_t& hp, uint32_t& lp) {
    asm("cvt.rn.bf16x2.f32 %0, %1, %2;" : "=r"(hp) : "f"(f1), "f"(f0));
    float h0 = __uint_as_float(hp << 16);
    float h1 = __uint_as_float(hp & 0xFFFF0000u);
    float l0 = f0 - h0, l1 = f1 - h1;
    asm("cvt.rn.bf16x2.f32 %0, %1, %2;" : "=r"(lp) : "f"(l1), "f"(l0));
}

// ---------------- prepass: x (fp32, K=160) -> g_ahi/g_alo (stride 192, zero-padded) ----------------
__global__ void k_prep_x(const float* __restrict__ x) {
    int idx = blockIdx.x * blockDim.x + threadIdx.x;
    if (idx >= N_NODES * 48) return;
    int row = idx / 48;
    int c = (idx % 48) * 4;
    float4 v = make_float4(0.f, 0.f, 0.f, 0.f);
    if (c < 160) v = *(const float4*)(x + (size_t)row * 160 + c);
    uint32_t h0, l0, h1, l1;
    split2(v.x, v.y, h0, l0);
    split2(v.z, v.w, h1, l1);
    uint32_t* ph = (uint32_t*)((char*)g_ahi + ((size_t)row * 192 + c) * 2);
    uint32_t* pl = (uint32_t*)((char*)g_alo + ((size_t)row * 192 + c) * 2);
    ph[0] = h0; ph[1] = h1;
    pl[0] = l0; pl[1] = l1;
}

// ---------------- prepass: weights [K,128]x2 -> g_bhi/g_blo transposed [256 x Kpad] ----------------
__global__ void k_prep_w(const float* __restrict__ wl, const float* __restrict__ wr,
                         int K, int Kpad) {
    int idx = blockIdx.x * blockDim.x + threadIdx.x;
    int total = 256 * (Kpad / 4);
    if (idx >= total) return;
    int n = idx / (Kpad / 4);
    int k = (idx % (Kpad / 4)) * 4;
    const float* W = (n < 128) ? wl : wr;
    int nc = n & 127;
    float f[4];
#pragma unroll
    for (int j = 0; j < 4; ++j)
        f[j] = (k + j < K) ? W[(size_t)(k + j) * 128 + nc] : 0.f;
    uint32_t h0, l0, h1, l1;
    split2(f[0], f[1], h0, l0);
    split2(f[2], f[3], h1, l1);
    uint32_t* ph = (uint32_t*)((char*)g_bhi + ((size_t)n * Kpad + k) * 2);
    uint32_t* pl = (uint32_t*)((char*)g_blo + ((size_t)n * Kpad + k) * 2);
    ph[0] = h0; ph[1] = h1;
    pl[0] = l0; pl[1] = l1;
}

// ---------------- tensor GEMM via mma.sync, cp.async 3-stage pipeline ----------------
// blockIdx.y==0 -> p half (fp16 to g_ph), ==1 -> q half (fp32 to g_q). 3 x 32KB smem buffers.
__global__ __launch_bounds__(256, 2) void k_mma(int stride, int nkc) {
    extern __shared__ __align__(1024) char sm[];
    const uint32_t smb = smem_to_u32(sm);

    const int tid = threadIdx.x;
    const int lane = tid & 31;
    const int wid = tid >> 5;
    const int wm = wid & 1;
    const int wn = wid >> 1;
    const int m0 = blockIdx.x * 128;
    const int nsel = blockIdx.y;
    const int total = 3 * nkc;

    float acc[4][4][4];
#pragma unroll
    for (int i = 0; i < 4; ++i)
#pragma unroll
        for (int j = 0; j < 4; ++j)
#pragma unroll
            for (int r = 0; r < 4; ++r) acc[i][j][r] = 0.f;

    const int a_row = wm * 64 + ((lane >> 3) & 1) * 8 + (lane & 7);
    const int a_c16 = lane >> 4;
    const int b_row = wn * 32 + (lane & 7);
    const int b_c16 = (lane >> 3) & 1;

    auto stage = [&](int ci, int buf) {
        int t = ci / nkc;
        int kc = ci - t * nkc;
        const char* Aarr = (const char*)((t < 2) ? g_ahi : g_alo);
        const char* Barr = (const char*)((t == 1) ? g_blo : g_bhi);
        int k0 = kc * 64;
        uint32_t Ab = smb + buf * 32768;
        uint32_t Bb = Ab + 16384;
#pragma unroll
        for (int it = 0; it < 4; ++it) {
            int idx = tid + it * 256;
            int row = idx >> 3, c16 = idx & 7;
            int grow = m0 + row;
            const char* src = Aarr + ((size_t)grow * stride + k0) * 2 + c16 * 16;
            uint32_t dst = Ab + sw128(row * 128 + c16 * 16);
            int zf = (grow < N_NODES) ? 16 : 0;
            asm volatile("cp.async.cg.shared.global [%0], [%1], 16, %2;"
                         :: "r"(dst), "l"(src), "r"(zf));
        }
#pragma unroll
        for (int it = 0; it < 4; ++it) {
            int idx = tid + it * 256;
            int row = idx >> 3, c16 = idx & 7;
            const char* src = Barr + ((size_t)(nsel * 128 + row) * stride + k0) * 2 + c16 * 16;
            uint32_t dst = Bb + sw128(row * 128 + c16 * 16);
            asm volatile("cp.async.cg.shared.global [%0], [%1], 16;"
                         :: "r"(dst), "l"(src));
        }
        asm volatile("cp.async.commit_group;" ::: "memory");
    };

    stage(0, 0);
    if (total > 1) stage(1, 1);
    for (int ci = 0; ci < total; ++ci) {
        if (ci + 2 < total) stage(ci + 2, (ci + 2) % 3);
        // ensure group ci complete; allow up to 2 younger groups in flight
        int rem = total - 1 - ci;
        if (rem >= 2)       asm volatile("cp.async.wait_group 2;" ::: "memory");
        else if (rem == 1)  asm volatile("cp.async.wait_group 1;" ::: "memory");
        else                asm volatile("cp.async.wait_group 0;" ::: "memory");
        __syncthreads();

        const uint32_t As = smb + (ci % 3) * 32768;
        const uint32_t Bs = As + 16384;
#pragma unroll
        for (int ks = 0; ks < 4; ++ks) {
            uint32_t af[4][4];
#pragma unroll
            for (int mt = 0; mt < 4; ++mt) {
                uint32_t addr = As + sw128((uint32_t)(a_row + mt * 16) * 128 +
                                           (uint32_t)(a_c16 + ks * 2) * 16);
                asm volatile("ldmatrix.sync.aligned.m8n8.x4.shared.b16 {%0,%1,%2,%3}, [%4];"
                             : "=r"(af[mt][0]), "=r"(af[mt][1]), "=r"(af[mt][2]), "=r"(af[mt][3])
                             : "r"(addr));
            }
            uint32_t bf[4][2];
#pragma unroll
            for (int nt = 0; nt < 4; ++nt) {
                uint32_t addr = Bs + sw128((uint32_t)(b_row + nt * 8) * 128 +
                                           (uint32_t)(b_c16 + ks * 2) * 16);
                asm volatile("ldmatrix.sync.aligned.m8n8.x2.shared.b16 {%0,%1}, [%2];"
                             : "=r"(bf[nt][0]), "=r"(bf[nt][1])
                             : "r"(addr));
            }
#pragma unroll
            for (int mt = 0; mt < 4; ++mt)
#pragma unroll
                for (int nt = 0; nt < 4; ++nt)
                    asm volatile(
                        "mma.sync.aligned.m16n8k16.row.col.f32.bf16.bf16.f32 "
                        "{%0,%1,%2,%3}, {%4,%5,%6,%7}, {%8,%9}, {%0,%1,%2,%3};"
                        : "+f"(acc[mt][nt][0]), "+f"(acc[mt][nt][1]),
                          "+f"(acc[mt][nt][2]), "+f"(acc[mt][nt][3])
                        : "r"(af[mt][0]), "r"(af[mt][1]), "r"(af[mt][2]), "r"(af[mt][3]),
                          "r"(bf[nt][0]), "r"(bf[nt][1]));
        }
        __syncthreads();
    }

    const int colb = wn * 32 + (lane & 3) * 2;
    const int rowb = m0 + wm * 64 + (lane >> 2);
    if (nsel == 0) {
#pragma unroll
        for (int mt = 0; mt < 4; ++mt) {
            int r0 = rowb + mt * 16;
            int r1 = r0 + 8;
#pragma unroll
            for (int nt = 0; nt < 4; ++nt) {
                int col = colb + nt * 8;
                if (r0 < N_NODES)
                    *(__half2*)(g_ph + (size_t)r0 * HID + col) =
                        __floats2half2_rn(acc[mt][nt][0], acc[mt][nt][1]);
                if (r1 < N_NODES)
                    *(__half2*)(g_ph + (size_t)r1 * HID + col) =
                        __floats2half2_rn(acc[mt][nt][2], acc[mt][nt][3]);
            }
        }
    } else {
#pragma unroll
        for (int mt = 0; mt < 4; ++mt) {
            int r0 = rowb + mt * 16;
            int r1 = r0 + 8;
#pragma unroll
            for (int nt = 0; nt < 4; ++nt) {
                int col = colb + nt * 8;
                if (r0 < N_NODES) {
                    float2 v; v.x = acc[mt][nt][0]; v.y = acc[mt][nt][1];
                    *(float2*)(g_q + (size_t)r0 * HID + col) = v;
                }
                if (r1 < N_NODES) {
                    float2 v; v.x = acc[mt][nt][2]; v.y = acc[mt][nt][3];
                    *(float2*)(g_q + (size_t)r1 * HID + col) = v;
                }
            }
        }
    }
}

// ---------------- fused aggregation + bias + BN + ReLU (+ hi/lo split or final head) ----------------
__global__ __launch_bounds__(256) void k_agg(const float* __restrict__ bl,
                                             const float* __restrict__ gam,
                                             const float* __restrict__ bet,
                                             const float* __restrict__ rm,
                                             const float* __restrict__ rv,
                                             const float* __restrict__ lin_w,
                                             const float* __restrict__ lin_b,
                                             float* __restrict__ out,
                                             int last) {
    int node = (blockIdx.x * blockDim.x + threadIdx.x) >> 5;
    if (node >= N_NODES) return;
    int lane = threadIdx.x & 31;
    int c = lane * 4;

    int s0 = g_rowptr[node];
    int s1 = g_rowptr[node + 1];
    float4 acc = make_float4(0.f, 0.f, 0.f, 0.f);
    int e = s0;
    // 8-wide software pipeline: 8 independent fp16 gathers (8B each) in flight
    for (; e + 8 <= s1; e += 8) {
        int i0 = g_srcs[e + 0], i1 = g_srcs[e + 1], i2 = g_srcs[e + 2], i3 = g_srcs[e + 3];
        int i4 = g_srcs[e + 4], i5 = g_srcs[e + 5], i6 = g_srcs[e + 6], i7 = g_srcs[e + 7];
        uint2 u0 = *(const uint2*)(g_ph + (size_t)i0 * HID + c);
        uint2 u1 = *(const uint2*)(g_ph + (size_t)i1 * HID + c);
        uint2 u2 = *(const uint2*)(g_ph + (size_t)i2 * HID + c);
        uint2 u3 = *(const uint2*)(g_ph + (size_t)i3 * HID + c);
        uint2 u4 = *(const uint2*)(g_ph + (size_t)i4 * HID + c);
        uint2 u5 = *(const uint2*)(g_ph + (size_t)i5 * HID + c);
        uint2 u6 = *(const uint2*)(g_ph + (size_t)i6 * HID + c);
        uint2 u7 = *(const uint2*)(g_ph + (size_t)i7 * HID + c);
#pragma unroll
        for (int j = 0; j < 8; ++j) {
            uint2 u = (j == 0) ? u0 : (j == 1) ? u1 : (j == 2) ? u2 : (j == 3) ? u3
                    : (j == 4) ? u4 : (j == 5) ? u5 : (j == 6) ? u6 : u7;
            float2 a = __half22float2(*(const __half2*)&u.x);
            float2 b = __half22float2(*(const __half2*)&u.y);
            acc.x += a.x; acc.y += a.y; acc.z += b.x; acc.w += b.y;
        }
    }
    for (; e < s1; ++e) {
        int s = g_srcs[e];
        uint2 u = *(const uint2*)(g_ph + (size_t)s * HID + c);
        float2 a = __half22float2(*(const __half2*)&u.x);
        float2 b = __half22float2(*(const __half2*)&u.y);
        acc.x += a.x; acc.y += a.y; acc.z += b.x; acc.w += b.y;
    }
    float inv = 1.f / (float)max(s1 - s0, 1);

    float4 q   = *(const float4*)(g_q + (size_t)node * HID + c);
    float4 vb  = *(const float4*)(bl + c);
    float4 vg  = *(const float4*)(gam + c);
    float4 vbe = *(const float4*)(bet + c);
    float4 vrm = *(const float4*)(rm + c);
    float4 vrv = *(const float4*)(rv + c);

    float o0 = acc.x * inv + q.x + vb.x;
    float o1 = acc.y * inv + q.y + vb.y;
    float o2 = acc.z * inv + q.z + vb.z;
    float o3 = acc.w * inv + q.w + vb.w;

    o0 = (o0 - vrm.x) * (vg.x * rsqrtf(vrv.x + BN_EPS)) + vbe.x;
    o1 = (o1 - vrm.y) * (vg.y * rsqrtf(vrv.y + BN_EPS)) + vbe.y;
    o2 = (o2 - vrm.z) * (vg.z * rsqrtf(vrv.z + BN_EPS)) + vbe.z;
    o3 = (o3 - vrm.w) * (vg.w * rsqrtf(vrv.w + BN_EPS)) + vbe.w;

    o0 = fmaxf(o0, 0.f); o1 = fmaxf(o1, 0.f);
    o2 = fmaxf(o2, 0.f); o3 = fmaxf(o3, 0.f);

    if (last) {
        float4 wv = *(const float4*)(lin_w + c);
        float s = o0 * wv.x + o1 * wv.y + o2 * wv.z + o3 * wv.w;
#pragma unroll
        for (int off = 16; off > 0; off >>= 1)
            s += __shfl_down_sync(0xffffffffu, s, off);
        if (lane == 0) out[node] = s + lin_b[0];
    } else {
        uint32_t h0, l0, h1, l1;
        split2(o0, o1, h0, l0);
        split2(o2, o3, h1, l1);
        uint2 hv; hv.x = h0; hv.y = h1;
        uint2 lv; lv.x = l0; lv.y = l1;
        *(uint2*)((char*)g_ahi + ((size_t)node * 128 + c) * 2) = hv;
        *(uint2*)((char*)g_alo + ((size_t)node * 128 + c) * 2) = lv;
    }
}

// ---------------- launch ----------------
extern "C" void kernel_launch(void* const* d_in, const int* in_sizes, int n_in,
                              void* d_out, int out_size) {
    const float* x  = (const float*)d_in[0];
    const int*   ei = (const int*)d_in[1];
    const float* wl[3]; const float* wr[3]; const float* bl[3];
    const float* gm[3]; const float* be[3]; const float* rm[3]; const float* rv[3];
    for (int i = 0; i < 3; ++i) {
        const int base = 2 + 7 * i;
        wl[i] = (const float*)d_in[base + 0];
        wr[i] = (const float*)d_in[base + 1];
        bl[i] = (const float*)d_in[base + 2];
        gm[i] = (const float*)d_in[base + 3];
        be[i] = (const float*)d_in[base + 4];
        rm[i] = (const float*)d_in[base + 5];
        rv[i] = (const float*)d_in[base + 6];
    }
    const float* lin_w = (const float*)d_in[23];
    const float* lin_b = (const float*)d_in[24];
    float* out = (float*)d_out;

    cudaFuncSetAttribute(k_mma, cudaFuncAttributeMaxDynamicSharedMemorySize, 98304);

    const int TB = 256;
    const int nb_nodes = (N_NODES + TB - 1) / TB;
    const int nb_edges = (N_EDGES + TB - 1) / TB;
    const int nb_warps = (N_NODES * 32 + TB - 1) / TB;

    // side stream for CSR build + weight prep (independent of main chain until joins)
    cudaStream_t s2;
    cudaStreamCreateWithFlags(&s2, cudaStreamNonBlocking);
    cudaEvent_t eFork, eJoin, eW1;
    cudaEventCreateWithFlags(&eFork, cudaEventDisableTiming);
    cudaEventCreateWithFlags(&eJoin, cudaEventDisableTiming);
    cudaEventCreateWithFlags(&eW1, cudaEventDisableTiming);

    cudaEventRecord(eFork, 0);
    cudaStreamWaitEvent(s2, eFork, 0);

    // CSR build on side stream
    k_zero_deg<<<nb_nodes, TB, 0, s2>>>();
    k_hist<<<nb_edges, TB, 0, s2>>>(ei);
    k_scan<<<1, 1024, 0, s2>>>();
    k_cursor_init<<<nb_nodes, TB, 0, s2>>>();
    k_place<<<nb_edges, TB, 0, s2>>>(ei);
    cudaEventRecord(eJoin, s2);

    dim3 ggrid(N_TILES, 2);
    // layer 0 prep + GEMM on main stream
    k_prep_x<<<(N_NODES * 48 + TB - 1) / TB, TB>>>(x);
    k_prep_w<<<(256 * 48 + TB - 1) / TB, TB>>>(wl[0], wr[0], 160, 192);
    k_mma<<<ggrid, 256, 98304>>>(192, 3);

    // prep layer-1 weights on side stream (after CSR kernels drain there;
    // safe: layer-0 mma has already consumed g_bhi/g_blo... only on main stream —
    // enforce ordering: side stream must wait until layer-0 mma is done before
    // overwriting the weight buffers)
    cudaEvent_t eM0;
    cudaEventCreateWithFlags(&eM0, cudaEventDisableTiming);
    cudaEventRecord(eM0, 0);
    cudaStreamWaitEvent(s2, eM0, 0);
    k_prep_w<<<(256 * 32 + TB - 1) / TB, TB, 0, s2>>>(wl[1], wr[1], 128, 128);
    cudaEventRecord(eW1, s2);

    cudaStreamWaitEvent(0, eJoin, 0);
    k_agg<<<nb_warps, TB>>>(bl[0], gm[0], be[0], rm[0], rv[0], lin_w, lin_b, out, 0);

    // layer 1: main stream waits for side-stream weight prep
    cudaStreamWaitEvent(0, eW1, 0);
    k_mma<<<ggrid, 256, 98304>>>(128, 2);
    k_agg<<<nb_warps, TB>>>(bl[1], gm[1], be[1], rm[1], rv[1], lin_w, lin_b, out, 0);
    // layer 2 (weight prep on main stream: previous mma already consumed buffers)
    k_prep_w<<<(256 * 32 + TB - 1) / TB, TB>>>(wl[2], wr[2], 128, 128);
    k_mma<<<ggrid, 256, 98304>>>(128, 2);
    k_agg<<<nb_warps, TB>>>(bl[2], gm[2], be[2], rm[2], rv[2], lin_w, lin_b, out, 1);
}